// round 1
// baseline (speedup 1.0000x reference)
#include <cuda_runtime.h>
#include <math.h>

#define DM   1024
#define NEXP 32
#define FE   128
#define TT   4
#define BATCH 4
#define SEQ  4096
#define NTOK (BATCH*SEQ)   // 16384
#define NGRP (SEQ/TT)      // 1024

typedef unsigned long long ull;

// logits transposed: [(b*4+t)*32 + e][g]  -> 16*32*1024 floats = 2MB
__device__ float g_logitsT[BATCH*TT*NEXP*NGRP];

__device__ __forceinline__ ull pack2(float a, float b) {
    ull r; asm("mov.b64 %0,{%1,%2};" : "=l"(r) : "f"(a), "f"(b)); return r;
}
__device__ __forceinline__ void unpack2(ull v, float& a, float& b) {
    asm("mov.b64 {%0,%1},%2;" : "=f"(a), "=f"(b) : "l"(v));
}
__device__ __forceinline__ void ffma2(ull& d, ull a, ull b) {
    asm("fma.rn.f32x2 %0,%1,%2,%0;" : "+l"(d) : "l"(a), "l"(b));
}

// ---------------------------------------------------------------------------
// K1: zero output + compute logits (token-parallel, k split in halves,
//     controller in smem as f32x2 pairs, x staged via smem transposed).
// grid = 128 blocks x 256 threads; block covers 128 tokens.
// ---------------------------------------------------------------------------
__global__ void __launch_bounds__(256, 1)
k_logits(const float* __restrict__ x, const float* __restrict__ ctrl,
         float* __restrict__ out)
{
    extern __shared__ char smraw[];
    ull*   ctrl_s = reinterpret_cast<ull*>(smraw);            // 1024*16 ull = 128KB
    ull*   red_s  = reinterpret_cast<ull*>(smraw + 131072);   // 128*16 ull  = 16KB
    float* x_s    = reinterpret_cast<float*>(smraw + 147456); // 64*129 f    = 33KB

    const int tid = threadIdx.x;

    // zero this block's slab of the output (128 tokens * 1024 floats)
    {
        float4 z = make_float4(0.f, 0.f, 0.f, 0.f);
        float4* op = reinterpret_cast<float4*>(out) + (size_t)blockIdx.x * (128*DM/4);
        #pragma unroll
        for (int i = 0; i < 128; i++) op[tid + i*256] = z;
    }

    // load controller (1024x32 f32) into smem; natural layout == pair layout
    {
        const float4* cg = reinterpret_cast<const float4*>(ctrl);
        float4* cs = reinterpret_cast<float4*>(ctrl_s);
        #pragma unroll
        for (int i = 0; i < 32; i++) cs[tid + i*256] = cg[tid + i*256];
    }

    const int tl = tid & 127;    // token-in-block
    const int kh = tid >> 7;     // k half (0: k<512, 1: k>=512)
    const int tok = blockIdx.x * 128 + tl;

    ull acc[16];
    #pragma unroll
    for (int i = 0; i < 16; i++) acc[i] = 0ull;

    const float* xbase = x + (size_t)blockIdx.x * 128 * DM;

    for (int c = 0; c < 16; c++) {           // 16 chunks of 32 k per half
        __syncthreads();
        // stage: 128 tokens x 64 k (32 per half), transposed [k][tok], pad 129
        #pragma unroll
        for (int i = 0; i < 8; i++) {
            int idx = tid + i*256;           // 0..2047
            int tk  = idx >> 4;              // token
            int seg = (idx >> 3) & 1;        // which half
            int off = idx & 7;               // float4 within 32-float window
            float4 v = *reinterpret_cast<const float4*>(
                xbase + (size_t)tk*DM + seg*512 + c*32 + off*4);
            int kk = seg*32 + off*4;
            x_s[(kk+0)*129 + tk] = v.x;
            x_s[(kk+1)*129 + tk] = v.y;
            x_s[(kk+2)*129 + tk] = v.z;
            x_s[(kk+3)*129 + tk] = v.w;
        }
        __syncthreads();

        const ull*   cb = ctrl_s + ((size_t)kh*512 + c*32) * 16;
        const float* xb = x_s + (kh*32)*129 + tl;
        #pragma unroll
        for (int kk = 0; kk < 32; kk++) {
            float xv = xb[kk*129];
            ull xx = pack2(xv, xv);
            const ull* cc = cb + kk*16;
            #pragma unroll
            for (int ep = 0; ep < 16; ep++) ffma2(acc[ep], xx, cc[ep]);
        }
    }

    // combine halves, add tiebreak, store transposed logits
    if (kh) {
        #pragma unroll
        for (int ep = 0; ep < 16; ep++) red_s[tl*16 + ep] = acc[ep];
    }
    __syncthreads();
    if (!kh) {
        int b = tok >> 12;
        int s = tok & 4095;
        int g = s >> 2;
        int t = s & 3;
        float tb = (float)t * (1e-6f / 3.0f);   // linspace(0,1e-6,4)[t]
        float* Lb = g_logitsT + ((size_t)((b*4 + t)*32) << 10) + g;
        #pragma unroll
        for (int ep = 0; ep < 16; ep++) {
            float a0, a1, b0, b1;
            unpack2(acc[ep], a0, a1);
            unpack2(red_s[tl*16 + ep], b0, b1);
            Lb[(size_t)(2*ep)   << 10] = a0 + b0 + tb;
            Lb[(size_t)(2*ep+1) << 10] = a1 + b1 + tb;
        }
    }
}

// ---------------------------------------------------------------------------
// K2: one block per (b,e): argmax+softmax over g for each t, then the two
//     expert matvecs, scatter-add into output.
// grid = 128 blocks x 128 threads.
// ---------------------------------------------------------------------------
__global__ void __launch_bounds__(128, 1)
k_expert(const float* __restrict__ x, const float* __restrict__ f1,
         const float* __restrict__ bias, const float* __restrict__ f2,
         float* __restrict__ out)
{
    __shared__ float xs[4][DM];
    __shared__ float W_s[4][FE];
    __shared__ int   s_g[4];
    __shared__ float s_p[4];
    __shared__ float wred[4];
    __shared__ int   wredi[4];

    const int tid  = threadIdx.x;
    const int lane = tid & 31;
    const int wid  = tid >> 5;
    const int b = blockIdx.x >> 5;
    const int e = blockIdx.x & 31;

    // ---- step 1: per t, argmax + softmax denominator over g ----
    for (int t = 0; t < 4; t++) {
        const float* L = g_logitsT + ((size_t)((b*4 + t)*32 + e) << 10);
        float m = -3.4e38f; int mi = 0;
        for (int i = tid; i < NGRP; i += 128) {
            float v = L[i];
            if (v > m) { m = v; mi = i; }
        }
        #pragma unroll
        for (int o = 16; o; o >>= 1) {
            float om = __shfl_down_sync(0xffffffffu, m, o);
            int   oi = __shfl_down_sync(0xffffffffu, mi, o);
            if (om > m || (om == m && oi < mi)) { m = om; mi = oi; }
        }
        if (lane == 0) { wred[wid] = m; wredi[wid] = mi; }
        __syncthreads();
        if (tid == 0) {
            for (int w = 1; w < 4; w++) {
                if (wred[w] > m || (wred[w] == m && wredi[w] < mi)) {
                    m = wred[w]; mi = wredi[w];
                }
            }
            wred[0] = m; wredi[0] = mi;
        }
        __syncthreads();
        m = wred[0]; mi = wredi[0];
        __syncthreads();

        float s = 0.f;
        for (int i = tid; i < NGRP; i += 128) s += expf(L[i] - m);
        #pragma unroll
        for (int o = 16; o; o >>= 1) s += __shfl_down_sync(0xffffffffu, s, o);
        if (lane == 0) wred[wid] = s;
        __syncthreads();
        if (tid == 0) {
            s_g[t] = mi;
            s_p[t] = 1.0f / (wred[0] + wred[1] + wred[2] + wred[3]);
        }
        __syncthreads();
    }

    // ---- step 2: load the 4 selected token rows into smem ----
    for (int t = 0; t < 4; t++) {
        const float* xr = x + ((size_t)b*SEQ + s_g[t]*4 + t) * DM;
        for (int i = tid; i < DM/4; i += 128)
            reinterpret_cast<float4*>(xs[t])[i] =
                reinterpret_cast<const float4*>(xr)[i];
    }
    __syncthreads();

    // ---- phase A: v_t[f] = x_t . f1[:,e,f]   (thread = f) ----
    float a0 = 0.f, a1 = 0.f, a2 = 0.f, a3 = 0.f;
    {
        const float* f1p = f1 + e*FE + tid;
        #pragma unroll 8
        for (int d = 0; d < DM; d++) {
            float w = f1p[(size_t)d * (NEXP*FE)];
            a0 += xs[0][d]*w; a1 += xs[1][d]*w;
            a2 += xs[2][d]*w; a3 += xs[3][d]*w;
        }
    }

    // ---- combine slots selecting the same group, relu, weight by p_t ----
    {
        float av[4] = {a0, a1, a2, a3};
        int   gg[4] = {s_g[0], s_g[1], s_g[2], s_g[3]};
        float pp[4] = {s_p[0], s_p[1], s_p[2], s_p[3]};
        float bi = bias[e*FE + tid];
        #pragma unroll
        for (int t = 0; t < 4; t++) {
            float sum = bi;
            #pragma unroll
            for (int t2 = 0; t2 < 4; t2++)
                if (gg[t2] == gg[t]) sum += pp[t2] * av[t2];
            W_s[t][tid] = pp[t] * fmaxf(sum, 0.f);
        }
    }
    __syncthreads();

    // ---- phase B: o_t[d'] = sum_f W_t[f] * f2[e,f,d']  (thread = 8 d') ----
    float o[4][8];
    #pragma unroll
    for (int t = 0; t < 4; t++)
        #pragma unroll
        for (int j = 0; j < 8; j++) o[t][j] = 0.f;

    const float* f2p = f2 + (size_t)e*FE*DM + tid*8;
    #pragma unroll 2
    for (int f = 0; f < FE; f++) {
        float4 v0 = *reinterpret_cast<const float4*>(f2p + (size_t)f*DM);
        float4 v1 = *reinterpret_cast<const float4*>(f2p + (size_t)f*DM + 4);
        #pragma unroll
        for (int t = 0; t < 4; t++) {
            float w = W_s[t][f];
            o[t][0] += w*v0.x; o[t][1] += w*v0.y;
            o[t][2] += w*v0.z; o[t][3] += w*v0.w;
            o[t][4] += w*v1.x; o[t][5] += w*v1.y;
            o[t][6] += w*v1.z; o[t][7] += w*v1.w;
        }
    }

    // ---- scatter-add into output rows ----
    #pragma unroll
    for (int t = 0; t < 4; t++) {
        float* orow = out + ((size_t)b*SEQ + s_g[t]*4 + t) * DM + tid*8;
        #pragma unroll
        for (int j = 0; j < 8; j++) atomicAdd(orow + j, o[t][j]);
    }
}

extern "C" void kernel_launch(void* const* d_in, const int* in_sizes, int n_in,
                              void* d_out, int out_size)
{
    const float* x    = (const float*)d_in[0];
    const float* ctrl = (const float*)d_in[1];
    const float* f1   = (const float*)d_in[2];
    const float* bias = (const float*)d_in[3];
    const float* f2   = (const float*)d_in[4];
    float* out = (float*)d_out;

    const int smem1 = 131072 + 16384 + 64*129*4;  // 180480 bytes
    cudaFuncSetAttribute(k_logits, cudaFuncAttributeMaxDynamicSharedMemorySize, smem1);

    k_logits<<<NTOK/128, 256, smem1>>>(x, ctrl, out);
    k_expert<<<BATCH*NEXP, 128>>>(x, f1, bias, f2, out);
}

// round 2
// speedup vs baseline: 1.1656x; 1.1656x over previous
#include <cuda_runtime.h>
#include <math.h>

#define DM   1024
#define NEXP 32
#define FE   128
#define TT   4
#define BATCH 4
#define SEQ  4096
#define NTOK (BATCH*SEQ)   // 16384
#define NGRP (SEQ/TT)      // 1024

typedef unsigned long long ull;

// scratch (device globals; no allocation)
__device__ float g_logitsT[BATCH*TT*NEXP*NGRP];          // 2MB  [(b*4+t)*32+e][g]
__device__ float g_W[BATCH*NEXP*TT*FE];                  // 256KB [be][t][f] (p-scaled, post-relu)
__device__ int   g_selg[BATCH*TT*NEXP];                  // [(b*4+t)*32+e] selected group
__device__ float g_inter[BATCH*NEXP*TT*DM];              // 2MB  [be][t][d]

__device__ __forceinline__ ull pack2(float a, float b) {
    ull r; asm("mov.b64 %0,{%1,%2};" : "=l"(r) : "f"(a), "f"(b)); return r;
}
__device__ __forceinline__ void unpack2(ull v, float& a, float& b) {
    asm("mov.b64 {%0,%1},%2;" : "=f"(a), "=f"(b) : "l"(v));
}
__device__ __forceinline__ void ffma2(ull& d, ull a, ull b) {
    asm("fma.rn.f32x2 %0,%1,%2,%0;" : "+l"(d) : "l"(a), "l"(b));
}

// ---------------------------------------------------------------------------
// K1: logits only. 128 blocks x 256 threads, 128 tokens/block,
// controller resident in smem, x staged transposed with reg double-buffering.
// ---------------------------------------------------------------------------
#define XBUF_F (64*129)              // floats per staging buffer
__global__ void __launch_bounds__(256, 1)
k_logits(const float* __restrict__ x, const float* __restrict__ ctrl)
{
    extern __shared__ char smraw[];
    ull*   ctrl_s = reinterpret_cast<ull*>(smraw);                 // 128KB
    float* xbuf0  = reinterpret_cast<float*>(smraw + 131072);      // 33KB
    float* xbuf1  = xbuf0 + XBUF_F;                                // 33KB
    ull*   red_s  = reinterpret_cast<ull*>(xbuf0);                 // alias (used after loop)

    const int tid = threadIdx.x;

    // load controller (1024x32 f32 = 512 float4) into smem
    {
        const float4* cg = reinterpret_cast<const float4*>(ctrl);
        float4* cs = reinterpret_cast<float4*>(ctrl_s);
        #pragma unroll
        for (int i = 0; i < 32; i++) cs[tid + i*256] = cg[tid + i*256];
    }

    const int tl = tid & 127;    // token-in-block
    const int kh = tid >> 7;     // k half
    const int tok = blockIdx.x * 128 + tl;
    const float* xbase = x + (size_t)blockIdx.x * 128 * DM;

    // per-thread staging geometry (fixed across chunks)
    const int s_tk  = tid >> 4;          // base token for i=0; tokens step by 16
    const int s_seg = (tid >> 3) & 1;
    const int s_off = tid & 7;
    const int s_kk  = s_seg*32 + s_off*4;

    ull acc[16];
    #pragma unroll
    for (int i = 0; i < 16; i++) acc[i] = 0ull;

    float4 r[8];
    // prologue: stage chunk 0
    #pragma unroll
    for (int i = 0; i < 8; i++)
        r[i] = *reinterpret_cast<const float4*>(
            xbase + (size_t)(s_tk + i*16)*DM + s_seg*512 + 0*32 + s_off*4);
    {
        float* bw = xbuf0;
        #pragma unroll
        for (int i = 0; i < 8; i++) {
            int tk = s_tk + i*16;
            bw[(s_kk+0)*129 + tk] = r[i].x;
            bw[(s_kk+1)*129 + tk] = r[i].y;
            bw[(s_kk+2)*129 + tk] = r[i].z;
            bw[(s_kk+3)*129 + tk] = r[i].w;
        }
    }
    __syncthreads();

    for (int c = 0; c < 16; c++) {
        // issue loads for next chunk first (latency hidden behind compute)
        if (c < 15) {
            #pragma unroll
            for (int i = 0; i < 8; i++)
                r[i] = *reinterpret_cast<const float4*>(
                    xbase + (size_t)(s_tk + i*16)*DM + s_seg*512 + (c+1)*32 + s_off*4);
        }
        // compute chunk c
        {
            const float* bufc = (c & 1) ? xbuf1 : xbuf0;
            const ull*   cb = ctrl_s + ((size_t)kh*512 + c*32) * 16;
            const float* xb = bufc + (kh*32)*129 + tl;
            #pragma unroll
            for (int kk = 0; kk < 32; kk++) {
                float xv = xb[kk*129];
                ull xx = pack2(xv, xv);
                const ull* cc = cb + kk*16;
                #pragma unroll
                for (int ep = 0; ep < 16; ep++) ffma2(acc[ep], xx, cc[ep]);
            }
        }
        // store next chunk into the other buffer
        if (c < 15) {
            float* bw = (c & 1) ? xbuf0 : xbuf1;
            #pragma unroll
            for (int i = 0; i < 8; i++) {
                int tk = s_tk + i*16;
                bw[(s_kk+0)*129 + tk] = r[i].x;
                bw[(s_kk+1)*129 + tk] = r[i].y;
                bw[(s_kk+2)*129 + tk] = r[i].z;
                bw[(s_kk+3)*129 + tk] = r[i].w;
            }
        }
        __syncthreads();
    }

    // combine halves, add tiebreak, store transposed logits
    if (kh) {
        #pragma unroll
        for (int ep = 0; ep < 16; ep++) red_s[tl*16 + ep] = acc[ep];
    }
    __syncthreads();
    if (!kh) {
        int b = tok >> 12;
        int s = tok & 4095;
        int g = s >> 2;
        int t = s & 3;
        float tb = (float)t * (1e-6f / 3.0f);   // linspace(0,1e-6,4)[t]
        float* Lb = g_logitsT + ((size_t)((b*4 + t)*32) << 10) + g;
        #pragma unroll
        for (int ep = 0; ep < 16; ep++) {
            float a0, a1, b0, b1;
            unpack2(acc[ep], a0, a1);
            unpack2(red_s[tl*16 + ep], b0, b1);
            Lb[(size_t)(2*ep)   << 10] = a0 + b0 + tb;
            Lb[(size_t)(2*ep+1) << 10] = a1 + b1 + tb;
        }
    }
}

// ---------------------------------------------------------------------------
// K2a: selection + up-projection. grid 128 (b,e) x 512 threads.
// ---------------------------------------------------------------------------
__global__ void __launch_bounds__(512, 1)
k_sel_up(const float* __restrict__ x, const float* __restrict__ f1,
         const float* __restrict__ bias)
{
    __shared__ float xs[4][DM];          // 16KB
    __shared__ float part[4][4][FE];     // [dc][t][f] 8KB
    __shared__ int   sg[4];
    __shared__ float sp[4];
    __shared__ float rm[4][4];           // per-t per-subwarp max
    __shared__ int   rmi[4][4];
    __shared__ float rs[4][4];           // per-t per-subwarp expsum

    const int tid  = threadIdx.x;
    const int lane = tid & 31;
    const int b = blockIdx.x >> 5;
    const int e = blockIdx.x & 31;

    // --- selection: 128-thread group per t ---
    {
        const int ts = tid >> 7;          // t handled by this group
        const int gt = tid & 127;
        const int sw = (tid >> 5) & 3;    // subwarp within group
        const float* L = g_logitsT + ((size_t)((b*4 + ts)*32 + e) << 10);

        float m = -3.4e38f; int mi = 0;
        #pragma unroll
        for (int j = 0; j < 8; j++) {
            int i = gt + j*128;
            float v = L[i];
            if (v > m) { m = v; mi = i; }
        }
        #pragma unroll
        for (int o = 16; o; o >>= 1) {
            float om = __shfl_down_sync(0xffffffffu, m, o);
            int   oi = __shfl_down_sync(0xffffffffu, mi, o);
            if (om > m || (om == m && oi < mi)) { m = om; mi = oi; }
        }
        if (lane == 0) { rm[ts][sw] = m; rmi[ts][sw] = mi; }
        __syncthreads();
        if (tid < 4) {
            float mm = rm[tid][0]; int mmi = rmi[tid][0];
            #pragma unroll
            for (int w = 1; w < 4; w++) {
                if (rm[tid][w] > mm || (rm[tid][w] == mm && rmi[tid][w] < mmi)) {
                    mm = rm[tid][w]; mmi = rmi[tid][w];
                }
            }
            rm[tid][0] = mm; sg[tid] = mmi;
            g_selg[(b*4 + tid)*32 + e] = mmi;
        }
        __syncthreads();
        m = rm[ts][0];

        float s = 0.f;
        #pragma unroll
        for (int j = 0; j < 8; j++) s += expf(L[gt + j*128] - m);
        #pragma unroll
        for (int o = 16; o; o >>= 1) s += __shfl_down_sync(0xffffffffu, s, o);
        if (lane == 0) rs[ts][sw] = s;
        __syncthreads();
        if (tid < 4)
            sp[tid] = 1.0f / (rs[tid][0] + rs[tid][1] + rs[tid][2] + rs[tid][3]);
        __syncthreads();
    }

    // --- load the 4 selected token rows into smem ---
    {
        const int ts = tid >> 7;
        const int gt = tid & 127;
        const float* xr = x + ((size_t)b*SEQ + sg[ts]*4 + ts) * DM;
        float4* dst = reinterpret_cast<float4*>(xs[ts]);
        const float4* src = reinterpret_cast<const float4*>(xr);
        dst[gt]       = src[gt];
        dst[gt + 128] = src[gt + 128];
    }
    __syncthreads();

    // --- up-projection: f = tid&127, dc = tid>>7 covers 256 d each ---
    {
        const int f  = tid & 127;
        const int dc = tid >> 7;
        float a0 = 0.f, a1 = 0.f, a2 = 0.f, a3 = 0.f;
        const float* f1p = f1 + (size_t)dc*256*(NEXP*FE) + e*FE + f;
        const float* x0 = xs[0] + dc*256;
        const float* x1 = xs[1] + dc*256;
        const float* x2 = xs[2] + dc*256;
        const float* x3 = xs[3] + dc*256;
        #pragma unroll 8
        for (int d = 0; d < 256; d++) {
            float w = f1p[(size_t)d * (NEXP*FE)];
            a0 += x0[d]*w; a1 += x1[d]*w; a2 += x2[d]*w; a3 += x3[d]*w;
        }
        part[dc][0][f] = a0; part[dc][1][f] = a1;
        part[dc][2][f] = a2; part[dc][3][f] = a3;
    }
    __syncthreads();

    if (tid < 128) {
        const int f = tid;
        float av[4];
        #pragma unroll
        for (int t = 0; t < 4; t++)
            av[t] = part[0][t][f] + part[1][t][f] + part[2][t][f] + part[3][t][f];
        int   gg[4] = {sg[0], sg[1], sg[2], sg[3]};
        float pp[4] = {sp[0], sp[1], sp[2], sp[3]};
        float bi = bias[e*FE + f];
        #pragma unroll
        for (int t = 0; t < 4; t++) {
            float sum = bi;
            #pragma unroll
            for (int t2 = 0; t2 < 4; t2++)
                if (gg[t2] == gg[t]) sum += pp[t2] * av[t2];
            g_W[((size_t)(b*NEXP + e)*4 + t)*FE + f] = pp[t] * fmaxf(sum, 0.f);
        }
    }
}

// ---------------------------------------------------------------------------
// K2b: down-projection. grid 512 = (b,e) x 4 d'-slices, 128 threads.
// ---------------------------------------------------------------------------
__global__ void __launch_bounds__(128, 1)
k_down(const float* __restrict__ f2)
{
    __shared__ float Ws[4*FE];

    const int be = blockIdx.x >> 2;        // b*32+e
    const int s  = blockIdx.x & 3;         // d' slice of 256
    const int e  = be & 31;
    const int tid = threadIdx.x;

    #pragma unroll
    for (int i = 0; i < 4; i++)
        Ws[tid + i*128] = g_W[(size_t)be*4*FE + tid + i*128];
    __syncthreads();

    const float* f2p = f2 + (size_t)e*FE*DM + s*256 + tid*2;
    float o00=0,o01=0,o10=0,o11=0,o20=0,o21=0,o30=0,o31=0;
    #pragma unroll 4
    for (int f = 0; f < FE; f++) {
        float2 v = *reinterpret_cast<const float2*>(f2p + (size_t)f*DM);
        float w0 = Ws[0*FE+f], w1 = Ws[1*FE+f], w2 = Ws[2*FE+f], w3 = Ws[3*FE+f];
        o00 += w0*v.x; o01 += w0*v.y;
        o10 += w1*v.x; o11 += w1*v.y;
        o20 += w2*v.x; o21 += w2*v.y;
        o30 += w3*v.x; o31 += w3*v.y;
    }
    float* ip = g_inter + ((size_t)be*4)*DM + s*256 + tid*2;
    reinterpret_cast<float2*>(ip + 0*DM)[0] = make_float2(o00, o01);
    reinterpret_cast<float2*>(ip + 1*DM)[0] = make_float2(o10, o11);
    reinterpret_cast<float2*>(ip + 2*DM)[0] = make_float2(o20, o21);
    reinterpret_cast<float2*>(ip + 3*DM)[0] = make_float2(o30, o31);
}

// ---------------------------------------------------------------------------
// K3: gather + write full output (every row written exactly once).
// grid 128 = (b, 32-group chunk), 256 threads.
// ---------------------------------------------------------------------------
__global__ void __launch_bounds__(256, 1)
k_out(float* __restrict__ out)
{
    __shared__ int sgs[4*32];   // [t][e]

    const int b  = blockIdx.x >> 5;
    const int gc = blockIdx.x & 31;
    const int tid = threadIdx.x;

    if (tid < 128) sgs[tid] = g_selg[b*128 + tid];
    __syncthreads();

    for (int r = 0; r < 128; r++) {
        const int g = gc*32 + (r >> 2);
        const int t = r & 3;
        float4 acc = make_float4(0.f, 0.f, 0.f, 0.f);
        #pragma unroll 8
        for (int e = 0; e < 32; e++) {
            if (sgs[t*32 + e] == g) {
                float4 v = reinterpret_cast<const float4*>(
                    g_inter + ((size_t)(b*NEXP + e)*4 + t)*DM)[tid];
                acc.x += v.x; acc.y += v.y; acc.z += v.z; acc.w += v.w;
            }
        }
        reinterpret_cast<float4*>(
            out + ((size_t)b*SEQ + g*4 + t)*DM)[tid] = acc;
    }
}

extern "C" void kernel_launch(void* const* d_in, const int* in_sizes, int n_in,
                              void* d_out, int out_size)
{
    const float* x    = (const float*)d_in[0];
    const float* ctrl = (const float*)d_in[1];
    const float* f1   = (const float*)d_in[2];
    const float* bias = (const float*)d_in[3];
    const float* f2   = (const float*)d_in[4];
    float* out = (float*)d_out;

    const int smem1 = 131072 + 2*XBUF_F*4;   // 128KB + 2*33KB = 197120 bytes
    cudaFuncSetAttribute(k_logits, cudaFuncAttributeMaxDynamicSharedMemorySize, smem1);

    k_logits<<<NTOK/128, 256, smem1>>>(x, ctrl);
    k_sel_up<<<BATCH*NEXP, 512>>>(x, f1, bias);
    k_down<<<BATCH*NEXP*4, 128>>>(f2);
    k_out<<<BATCH*NGRP/32, 256>>>(out);
}

// round 3
// speedup vs baseline: 1.8621x; 1.5975x over previous
#include <cuda_runtime.h>
#include <math.h>

#define DM   1024
#define NEXP 32
#define FE   128
#define TT   4
#define BATCH 4
#define SEQ  4096
#define NTOK (BATCH*SEQ)   // 16384
#define NGRP (SEQ/TT)      // 1024

typedef unsigned long long ull;

// scratch (device globals; no allocation)
__device__ float g_logitsT[BATCH*TT*NEXP*NGRP];          // 2MB  [(b*4+t)*32+e][g]
__device__ float g_W[BATCH*NEXP*TT*FE];                  // 256KB [be][t][f] (p-scaled, post-relu)
__device__ int   g_selg[BATCH*TT*NEXP];                  // [(b*4+t)*32+e] selected group

__device__ __forceinline__ ull pack2(float a, float b) {
    ull r; asm("mov.b64 %0,{%1,%2};" : "=l"(r) : "f"(a), "f"(b)); return r;
}
__device__ __forceinline__ void unpack2(ull v, float& a, float& b) {
    asm("mov.b64 {%0,%1},%2;" : "=f"(a), "=f"(b) : "l"(v));
}
__device__ __forceinline__ void ffma2(ull& d, ull a, ull b) {
    asm("fma.rn.f32x2 %0,%1,%2,%0;" : "+l"(d) : "l"(a), "l"(b));
}

// ---------------------------------------------------------------------------
// K1: zero output slab + logits. 128 blocks x 256 threads, 128 tokens/block,
// controller resident in smem, x staged transposed with reg double-buffering.
// ---------------------------------------------------------------------------
#define XBUF_F (64*129)              // floats per staging buffer
__global__ void __launch_bounds__(256, 1)
k_logits(const float* __restrict__ x, const float* __restrict__ ctrl,
         float* __restrict__ out)
{
    extern __shared__ char smraw[];
    ull*   ctrl_s = reinterpret_cast<ull*>(smraw);                 // 128KB
    float* xbuf0  = reinterpret_cast<float*>(smraw + 131072);      // 33KB
    float* xbuf1  = xbuf0 + XBUF_F;                                // 33KB
    ull*   red_s  = reinterpret_cast<ull*>(xbuf0);                 // alias (used after loop)

    const int tid = threadIdx.x;

    // fire-and-forget zero of this block's output slab (128 tokens * 1024 f)
    {
        float4 z = make_float4(0.f, 0.f, 0.f, 0.f);
        float4* op = reinterpret_cast<float4*>(out) + (size_t)blockIdx.x * (128*DM/4);
        #pragma unroll
        for (int i = 0; i < 128; i++) op[tid + i*256] = z;
    }

    // load controller (1024x32 f32 = 512 float4) into smem
    {
        const float4* cg = reinterpret_cast<const float4*>(ctrl);
        float4* cs = reinterpret_cast<float4*>(ctrl_s);
        #pragma unroll
        for (int i = 0; i < 32; i++) cs[tid + i*256] = cg[tid + i*256];
    }

    const int tl = tid & 127;    // token-in-block
    const int kh = tid >> 7;     // k half
    const int tok = blockIdx.x * 128 + tl;
    const float* xbase = x + (size_t)blockIdx.x * 128 * DM;

    // per-thread staging geometry (fixed across chunks)
    const int s_tk  = tid >> 4;
    const int s_seg = (tid >> 3) & 1;
    const int s_off = tid & 7;
    const int s_kk  = s_seg*32 + s_off*4;

    ull acc[16];
    #pragma unroll
    for (int i = 0; i < 16; i++) acc[i] = 0ull;

    float4 r[8];
    #pragma unroll
    for (int i = 0; i < 8; i++)
        r[i] = *reinterpret_cast<const float4*>(
            xbase + (size_t)(s_tk + i*16)*DM + s_seg*512 + s_off*4);
    {
        float* bw = xbuf0;
        #pragma unroll
        for (int i = 0; i < 8; i++) {
            int tk = s_tk + i*16;
            bw[(s_kk+0)*129 + tk] = r[i].x;
            bw[(s_kk+1)*129 + tk] = r[i].y;
            bw[(s_kk+2)*129 + tk] = r[i].z;
            bw[(s_kk+3)*129 + tk] = r[i].w;
        }
    }
    __syncthreads();

    for (int c = 0; c < 16; c++) {
        if (c < 15) {
            #pragma unroll
            for (int i = 0; i < 8; i++)
                r[i] = *reinterpret_cast<const float4*>(
                    xbase + (size_t)(s_tk + i*16)*DM + s_seg*512 + (c+1)*32 + s_off*4);
        }
        {
            const float* bufc = (c & 1) ? xbuf1 : xbuf0;
            const ull*   cb = ctrl_s + ((size_t)kh*512 + c*32) * 16;
            const float* xb = bufc + (kh*32)*129 + tl;
            #pragma unroll
            for (int kk = 0; kk < 32; kk++) {
                float xv = xb[kk*129];
                ull xx = pack2(xv, xv);
                const ull* cc = cb + kk*16;
                #pragma unroll
                for (int ep = 0; ep < 16; ep++) ffma2(acc[ep], xx, cc[ep]);
            }
        }
        if (c < 15) {
            float* bw = (c & 1) ? xbuf0 : xbuf1;
            #pragma unroll
            for (int i = 0; i < 8; i++) {
                int tk = s_tk + i*16;
                bw[(s_kk+0)*129 + tk] = r[i].x;
                bw[(s_kk+1)*129 + tk] = r[i].y;
                bw[(s_kk+2)*129 + tk] = r[i].z;
                bw[(s_kk+3)*129 + tk] = r[i].w;
            }
        }
        __syncthreads();
    }

    if (kh) {
        #pragma unroll
        for (int ep = 0; ep < 16; ep++) red_s[tl*16 + ep] = acc[ep];
    }
    __syncthreads();
    if (!kh) {
        int b = tok >> 12;
        int s = tok & 4095;
        int g = s >> 2;
        int t = s & 3;
        float tb = (float)t * (1e-6f / 3.0f);   // linspace(0,1e-6,4)[t]
        float* Lb = g_logitsT + ((size_t)((b*4 + t)*32) << 10) + g;
        #pragma unroll
        for (int ep = 0; ep < 16; ep++) {
            float a0, a1, b0, b1;
            unpack2(acc[ep], a0, a1);
            unpack2(red_s[tl*16 + ep], b0, b1);
            Lb[(size_t)(2*ep)   << 10] = a0 + b0 + tb;
            Lb[(size_t)(2*ep+1) << 10] = a1 + b1 + tb;
        }
    }
}

// ---------------------------------------------------------------------------
// K2a: selection + up-projection. grid 128 (b,e) x 512 threads.
// f1 loop: float4 over f, 16-way warp split over d.
// ---------------------------------------------------------------------------
#define SMEM2 ((4*DM + 16*4*FE) * 4)   // xs 16KB + part 32KB = 49152
__global__ void __launch_bounds__(512, 1)
k_sel_up(const float* __restrict__ x, const float* __restrict__ f1,
         const float* __restrict__ bias)
{
    extern __shared__ float dsm[];
    float* xs   = dsm;            // [4][DM]
    float* part = dsm + 4*DM;     // [16][4][FE]

    __shared__ int   sg[4];
    __shared__ float sp[4];
    __shared__ float rm[4][4];
    __shared__ int   rmi[4][4];
    __shared__ float rs[4][4];

    const int tid  = threadIdx.x;
    const int lane = tid & 31;
    const int b = blockIdx.x >> 5;
    const int e = blockIdx.x & 31;

    // --- selection: 128-thread group per t ---
    {
        const int ts = tid >> 7;
        const int gt = tid & 127;
        const int sw = (tid >> 5) & 3;
        const float* L = g_logitsT + ((size_t)((b*4 + ts)*32 + e) << 10);

        float m = -3.4e38f; int mi = 0;
        #pragma unroll
        for (int j = 0; j < 8; j++) {
            int i = gt + j*128;
            float v = L[i];
            if (v > m) { m = v; mi = i; }
        }
        #pragma unroll
        for (int o = 16; o; o >>= 1) {
            float om = __shfl_down_sync(0xffffffffu, m, o);
            int   oi = __shfl_down_sync(0xffffffffu, mi, o);
            if (om > m || (om == m && oi < mi)) { m = om; mi = oi; }
        }
        if (lane == 0) { rm[ts][sw] = m; rmi[ts][sw] = mi; }
        __syncthreads();
        if (tid < 4) {
            float mm = rm[tid][0]; int mmi = rmi[tid][0];
            #pragma unroll
            for (int w = 1; w < 4; w++) {
                if (rm[tid][w] > mm || (rm[tid][w] == mm && rmi[tid][w] < mmi)) {
                    mm = rm[tid][w]; mmi = rmi[tid][w];
                }
            }
            rm[tid][0] = mm; sg[tid] = mmi;
            g_selg[(b*4 + tid)*32 + e] = mmi;
        }
        __syncthreads();
        m = rm[ts][0];

        float s = 0.f;
        #pragma unroll
        for (int j = 0; j < 8; j++) s += expf(L[gt + j*128] - m);
        #pragma unroll
        for (int o = 16; o; o >>= 1) s += __shfl_down_sync(0xffffffffu, s, o);
        if (lane == 0) rs[ts][sw] = s;
        __syncthreads();
        if (tid < 4)
            sp[tid] = 1.0f / (rs[tid][0] + rs[tid][1] + rs[tid][2] + rs[tid][3]);
        __syncthreads();
    }

    // --- load the 4 selected token rows into smem ---
    {
        const int ts = tid >> 7;
        const int gt = tid & 127;
        const float* xr = x + ((size_t)b*SEQ + sg[ts]*4 + ts) * DM;
        float4* dst = reinterpret_cast<float4*>(xs + ts*DM);
        const float4* src = reinterpret_cast<const float4*>(xr);
        dst[gt]       = src[gt];
        dst[gt + 128] = src[gt + 128];
    }
    __syncthreads();

    // --- up-projection: warp w covers d in [w*64, w*64+64), lane = f/4 ---
    {
        const int w = tid >> 5;
        float4 A0 = {0,0,0,0}, A1 = {0,0,0,0}, A2 = {0,0,0,0}, A3 = {0,0,0,0};
        const float4* f1p = reinterpret_cast<const float4*>(
            f1 + (size_t)(w*64)*(NEXP*FE) + e*FE) + lane;
        const float* x0 = xs + 0*DM + w*64;
        const float* x1 = xs + 1*DM + w*64;
        const float* x2 = xs + 2*DM + w*64;
        const float* x3 = xs + 3*DM + w*64;
        #pragma unroll 8
        for (int d = 0; d < 64; d++) {
            float4 wv = f1p[(size_t)d * (NEXP*FE/4)];
            float v0 = x0[d], v1 = x1[d], v2 = x2[d], v3 = x3[d];
            A0.x += v0*wv.x; A0.y += v0*wv.y; A0.z += v0*wv.z; A0.w += v0*wv.w;
            A1.x += v1*wv.x; A1.y += v1*wv.y; A1.z += v1*wv.z; A1.w += v1*wv.w;
            A2.x += v2*wv.x; A2.y += v2*wv.y; A2.z += v2*wv.z; A2.w += v2*wv.w;
            A3.x += v3*wv.x; A3.y += v3*wv.y; A3.z += v3*wv.z; A3.w += v3*wv.w;
        }
        float4* pp = reinterpret_cast<float4*>(part);
        pp[(w*4 + 0)*32 + lane] = A0;
        pp[(w*4 + 1)*32 + lane] = A1;
        pp[(w*4 + 2)*32 + lane] = A2;
        pp[(w*4 + 3)*32 + lane] = A3;
    }
    __syncthreads();

    if (tid < 128) {
        const int f = tid;
        float av[4];
        #pragma unroll
        for (int t = 0; t < 4; t++) {
            float s = 0.f;
            #pragma unroll
            for (int w = 0; w < 16; w++) s += part[(w*4 + t)*FE + f];
            av[t] = s;
        }
        int   gg[4] = {sg[0], sg[1], sg[2], sg[3]};
        float pp[4] = {sp[0], sp[1], sp[2], sp[3]};
        float bi = bias[e*FE + f];
        #pragma unroll
        for (int t = 0; t < 4; t++) {
            float sum = bi;
            #pragma unroll
            for (int t2 = 0; t2 < 4; t2++)
                if (gg[t2] == gg[t]) sum += pp[t2] * av[t2];
            g_W[((size_t)(b*NEXP + e)*4 + t)*FE + f] = pp[t] * fmaxf(sum, 0.f);
        }
    }
}

// ---------------------------------------------------------------------------
// K2b: down-projection + scatter-add into out.
// grid 512 = (b,e) x 4 d'-slices, 128 threads.
// ---------------------------------------------------------------------------
__global__ void __launch_bounds__(128, 1)
k_down(const float* __restrict__ f2, float* __restrict__ out)
{
    __shared__ float Ws[4*FE];
    __shared__ int   sg[4];

    const int be = blockIdx.x >> 2;        // b*32+e
    const int s  = blockIdx.x & 3;         // d' slice of 256
    const int b  = be >> 5;
    const int e  = be & 31;
    const int tid = threadIdx.x;

    #pragma unroll
    for (int i = 0; i < 4; i++)
        Ws[tid + i*128] = g_W[(size_t)be*4*FE + tid + i*128];
    if (tid < 4) sg[tid] = g_selg[(b*4 + tid)*32 + e];
    __syncthreads();

    const float* f2p = f2 + (size_t)e*FE*DM + s*256 + tid*2;
    float o00=0,o01=0,o10=0,o11=0,o20=0,o21=0,o30=0,o31=0;
    #pragma unroll 4
    for (int f = 0; f < FE; f++) {
        float2 v = *reinterpret_cast<const float2*>(f2p + (size_t)f*DM);
        float w0 = Ws[0*FE+f], w1 = Ws[1*FE+f], w2 = Ws[2*FE+f], w3 = Ws[3*FE+f];
        o00 += w0*v.x; o01 += w0*v.y;
        o10 += w1*v.x; o11 += w1*v.y;
        o20 += w2*v.x; o21 += w2*v.y;
        o30 += w3*v.x; o31 += w3*v.y;
    }

    float* ob = out + (size_t)b*SEQ*DM + s*256 + tid*2;
    float* r0 = ob + (size_t)(sg[0]*4 + 0)*DM;
    float* r1 = ob + (size_t)(sg[1]*4 + 1)*DM;
    float* r2 = ob + (size_t)(sg[2]*4 + 2)*DM;
    float* r3 = ob + (size_t)(sg[3]*4 + 3)*DM;
    atomicAdd(r0,   o00); atomicAdd(r0+1, o01);
    atomicAdd(r1,   o10); atomicAdd(r1+1, o11);
    atomicAdd(r2,   o20); atomicAdd(r2+1, o21);
    atomicAdd(r3,   o30); atomicAdd(r3+1, o31);
}

extern "C" void kernel_launch(void* const* d_in, const int* in_sizes, int n_in,
                              void* d_out, int out_size)
{
    const float* x    = (const float*)d_in[0];
    const float* ctrl = (const float*)d_in[1];
    const float* f1   = (const float*)d_in[2];
    const float* bias = (const float*)d_in[3];
    const float* f2   = (const float*)d_in[4];
    float* out = (float*)d_out;

    const int smem1 = 131072 + 2*XBUF_F*4;   // 197120 bytes
    cudaFuncSetAttribute(k_logits, cudaFuncAttributeMaxDynamicSharedMemorySize, smem1);
    cudaFuncSetAttribute(k_sel_up, cudaFuncAttributeMaxDynamicSharedMemorySize, SMEM2);

    k_logits<<<NTOK/128, 256, smem1>>>(x, ctrl, out);
    k_sel_up<<<BATCH*NEXP, 512, SMEM2>>>(x, f1, bias);
    k_down<<<BATCH*NEXP*4, 128>>>(f2, out);
}

// round 5
// speedup vs baseline: 2.1288x; 1.1432x over previous
#include <cuda_runtime.h>
#include <cstdint>
#include <math.h>

#define DM   1024
#define NEXP 32
#define FE   128
#define TT   4
#define BATCH 4
#define SEQ  4096
#define NTOK (BATCH*SEQ)   // 16384
#define NGRP (SEQ/TT)      // 1024

typedef unsigned long long ull;

// scratch (device globals; no allocation)
__device__ float g_logitsT[BATCH*TT*NEXP*NGRP];          // 2MB  [(b*4+t)*32+e][g]

__device__ __forceinline__ ull pack2(float a, float b) {
    ull r; asm("mov.b64 %0,{%1,%2};" : "=l"(r) : "f"(a), "f"(b)); return r;
}
__device__ __forceinline__ void unpack2(ull v, float& a, float& b) {
    asm("mov.b64 {%0,%1},%2;" : "=f"(a), "=f"(b) : "l"(v));
}
__device__ __forceinline__ void ffma2(ull& d, ull a, ull b) {
    asm("fma.rn.f32x2 %0,%1,%2,%0;" : "+l"(d) : "l"(a), "l"(b));
}
__device__ __forceinline__ void cp_async16(unsigned int dst, const void* src) {
    asm volatile("cp.async.cg.shared.global [%0], [%1], 16;\n" :: "r"(dst), "l"(src));
}
#define CP_COMMIT() asm volatile("cp.async.commit_group;\n" ::)
#define CP_WAIT0()  asm volatile("cp.async.wait_group 0;\n" ::)

// ---------------------------------------------------------------------------
// K1: zero output + logits GEMM, register-tiled.
// 256 blocks = 128 token-tiles x 2 expert-halves, 256 threads.
// Thread: 4 tokens x 16 experts (8 f32x2 pairs), k split 8-way across warps.
// smem: ctrl half [1024k][16e] = 64KB; x staged [tok][k] rows of 36 floats,
// double-buffered 32-k chunks via cp.async.
// ---------------------------------------------------------------------------
#define XROW 36
#define XBUF_BYTES (128*XROW*4)          // 18432
#define SMEM1 (65536 + 2*XBUF_BYTES)     // 102400

__global__ void __launch_bounds__(256, 2)
k_logits(const float* __restrict__ x, const float* __restrict__ ctrl,
         float* __restrict__ out)
{
    extern __shared__ char smraw[];
    ull*   ctrl_s = reinterpret_cast<ull*>(smraw);              // 64KB
    float* xbuf0  = reinterpret_cast<float*>(smraw + 65536);
    float* xbuf1  = reinterpret_cast<float*>(smraw + 65536 + XBUF_BYTES);

    const int tid = threadIdx.x;
    const int tg  = tid & 31;        // token group (lane)
    const int ks  = tid >> 5;        // k sub-slice (warp id), 0..7
    const int eh  = blockIdx.x & 1;  // expert half
    const int tb  = blockIdx.x >> 1; // token tile (128 tokens)
    const float* xblk = x + (size_t)tb * 128 * DM;

    // fire-and-forget zero of a 1/256 slab of out
    {
        float4 z = make_float4(0.f, 0.f, 0.f, 0.f);
        float4* op = reinterpret_cast<float4*>(out) + (size_t)blockIdx.x * 16384;
        #pragma unroll
        for (int i = 0; i < 64; i++) op[tid + i*256] = z;
    }

    const unsigned int xs0 = (unsigned int)__cvta_generic_to_shared(xbuf0);
    const unsigned int xs1 = (unsigned int)__cvta_generic_to_shared(xbuf1);
    const int stok = tid >> 3;       // staging token (0..31 base)
    const int sk4  = tid & 7;        // staging k-quad

    // stage chunk 0
    {
        #pragma unroll
        for (int i = 0; i < 4; i++) {
            int tok = stok + i*32;
            cp_async16(xs0 + tok*144 + sk4*16,
                       xblk + (size_t)tok*DM + sk4*4);
        }
        CP_COMMIT();
    }

    // load controller half into smem: [k][16 floats] = [k][8 ull]
    {
        const float4* cg4 = reinterpret_cast<const float4*>(ctrl);
        float4* cs4 = reinterpret_cast<float4*>(ctrl_s);
        #pragma unroll
        for (int i = 0; i < 16; i++) {
            int q = tid + i*256;                  // 0..4095
            cs4[q] = cg4[(q >> 2)*8 + eh*4 + (q & 3)];
        }
    }

    ull acc[4][8];
    #pragma unroll
    for (int i = 0; i < 4; i++)
        #pragma unroll
        for (int p = 0; p < 8; p++) acc[i][p] = 0ull;

    for (int c = 0; c < 32; c++) {
        CP_WAIT0();
        __syncthreads();
        if (c < 31) {
            unsigned int dst = ((c+1) & 1) ? xs1 : xs0;
            #pragma unroll
            for (int i = 0; i < 4; i++) {
                int tok = stok + i*32;
                cp_async16(dst + tok*144 + sk4*16,
                           xblk + (size_t)tok*DM + (c+1)*32 + sk4*4);
            }
            CP_COMMIT();
        }
        const float* xb = (c & 1) ? xbuf1 : xbuf0;
        float4 xv[4];
        #pragma unroll
        for (int i = 0; i < 4; i++)
            xv[i] = *reinterpret_cast<const float4*>(xb + (tg + 32*i)*XROW + ks*4);

        #pragma unroll
        for (int u = 0; u < 4; u++) {
            const ull* cp_ = ctrl_s + (size_t)(c*32 + ks*4 + u) * 8;
            ull cu[8];
            #pragma unroll
            for (int p = 0; p < 8; p++) cu[p] = cp_[p];
            ull x2[4];
            #pragma unroll
            for (int i = 0; i < 4; i++) {
                float xf = reinterpret_cast<const float*>(&xv[i])[u];
                x2[i] = pack2(xf, xf);
            }
            #pragma unroll
            for (int i = 0; i < 4; i++)
                #pragma unroll
                for (int p = 0; p < 8; p++) ffma2(acc[i][p], x2[i], cu[p]);
        }
    }
    __syncthreads();

    // reduce over the 8 k-slices through smem (reuse ctrl_s region)
    ull* red = ctrl_s;
    #pragma unroll
    for (int i = 0; i < 4; i++)
        #pragma unroll
        for (int p = 0; p < 8; p++)
            red[(size_t)ks*1024 + (tg + 32*i)*8 + p] = acc[i][p];
    __syncthreads();

    #pragma unroll
    for (int j = 0; j < 4; j++) {
        int s = tid*4 + j;               // 0..1023
        int tok = s >> 3, p = s & 7;
        float lo = 0.f, hi = 0.f;
        #pragma unroll
        for (int k2 = 0; k2 < 8; k2++) {
            float a, b;
            unpack2(red[(size_t)k2*1024 + s], a, b);
            lo += a; hi += b;
        }
        int gt = tb*128 + tok;
        int b  = gt >> 12;
        int sg = gt & 4095;
        int g  = sg >> 2, t = sg & 3;
        float tbk = (float)t * (1e-6f / 3.0f);   // linspace(0,1e-6,4)[t]
        int row = (b*4 + t)*32 + eh*16 + 2*p;
        g_logitsT[(size_t)row*1024 + g]     = lo + tbk;
        g_logitsT[(size_t)(row+1)*1024 + g] = hi + tbk;
    }
}

// ---------------------------------------------------------------------------
// K2: fused selection + up-projection + down-projection + scatter-add.
// grid 128 (b,e) x 512 threads.
// ---------------------------------------------------------------------------
#define SMEM2 ((4*DM + 16*4*FE + 4*FE) * 4)   // 16KB + 32KB + 2KB = 51200
__global__ void __launch_bounds__(512, 1)
k_expert(const float* __restrict__ x, const float* __restrict__ f1,
         const float* __restrict__ bias, const float* __restrict__ f2,
         float* __restrict__ out)
{
    extern __shared__ float dsm[];
    float* xs   = dsm;                 // [4][DM]
    float* part = dsm + 4*DM;          // [16][4][FE]
    float* Wsm  = part + 16*4*FE;      // [4][FE]

    __shared__ int   sg[4];
    __shared__ float sp[4];
    __shared__ float rm[4][4];
    __shared__ int   rmi[4][4];
    __shared__ float rs[4][4];

    const int tid  = threadIdx.x;
    const int lane = tid & 31;
    const int b = blockIdx.x >> 5;
    const int e = blockIdx.x & 31;

    // --- selection: 128-thread group per t ---
    {
        const int ts = tid >> 7;
        const int gt = tid & 127;
        const int sw = (tid >> 5) & 3;
        const float* L = g_logitsT + ((size_t)((b*4 + ts)*32 + e) << 10);

        float m = -3.4e38f; int mi = 0;
        #pragma unroll
        for (int j = 0; j < 8; j++) {
            int i = gt + j*128;
            float v = L[i];
            if (v > m) { m = v; mi = i; }
        }
        #pragma unroll
        for (int o = 16; o; o >>= 1) {
            float om = __shfl_down_sync(0xffffffffu, m, o);
            int   oi = __shfl_down_sync(0xffffffffu, mi, o);
            if (om > m || (om == m && oi < mi)) { m = om; mi = oi; }
        }
        if (lane == 0) { rm[ts][sw] = m; rmi[ts][sw] = mi; }
        __syncthreads();
        if (tid < 4) {
            float mm = rm[tid][0]; int mmi = rmi[tid][0];
            #pragma unroll
            for (int w = 1; w < 4; w++) {
                if (rm[tid][w] > mm || (rm[tid][w] == mm && rmi[tid][w] < mmi)) {
                    mm = rm[tid][w]; mmi = rmi[tid][w];
                }
            }
            rm[tid][0] = mm; sg[tid] = mmi;
        }
        __syncthreads();
        m = rm[ts][0];

        float s = 0.f;
        #pragma unroll
        for (int j = 0; j < 8; j++) s += expf(L[gt + j*128] - m);
        #pragma unroll
        for (int o = 16; o; o >>= 1) s += __shfl_down_sync(0xffffffffu, s, o);
        if (lane == 0) rs[ts][sw] = s;
        __syncthreads();
        if (tid < 4)
            sp[tid] = 1.0f / (rs[tid][0] + rs[tid][1] + rs[tid][2] + rs[tid][3]);
        __syncthreads();
    }

    // --- load the 4 selected token rows into smem ---
    {
        const int ts = tid >> 7;
        const int gt = tid & 127;
        const float* xr = x + ((size_t)b*SEQ + sg[ts]*4 + ts) * DM;
        float4* dst = reinterpret_cast<float4*>(xs + ts*DM);
        const float4* src = reinterpret_cast<const float4*>(xr);
        dst[gt]       = src[gt];
        dst[gt + 128] = src[gt + 128];
    }
    __syncthreads();

    // --- up-projection: warp w covers d in [w*64, w*64+64), lane = f/4 ---
    {
        const int w = tid >> 5;
        float4 A0 = {0,0,0,0}, A1 = {0,0,0,0}, A2 = {0,0,0,0}, A3 = {0,0,0,0};
        const float4* f1p = reinterpret_cast<const float4*>(
            f1 + (size_t)(w*64)*(NEXP*FE) + e*FE) + lane;
        const float* x0 = xs + 0*DM + w*64;
        const float* x1 = xs + 1*DM + w*64;
        const float* x2 = xs + 2*DM + w*64;
        const float* x3 = xs + 3*DM + w*64;
        #pragma unroll 8
        for (int d = 0; d < 64; d++) {
            float4 wv = f1p[(size_t)d * (NEXP*FE/4)];
            float v0 = x0[d], v1 = x1[d], v2 = x2[d], v3 = x3[d];
            A0.x += v0*wv.x; A0.y += v0*wv.y; A0.z += v0*wv.z; A0.w += v0*wv.w;
            A1.x += v1*wv.x; A1.y += v1*wv.y; A1.z += v1*wv.z; A1.w += v1*wv.w;
            A2.x += v2*wv.x; A2.y += v2*wv.y; A2.z += v2*wv.z; A2.w += v2*wv.w;
            A3.x += v3*wv.x; A3.y += v3*wv.y; A3.z += v3*wv.z; A3.w += v3*wv.w;
        }
        float4* pp = reinterpret_cast<float4*>(part);
        pp[(w*4 + 0)*32 + lane] = A0;
        pp[(w*4 + 1)*32 + lane] = A1;
        pp[(w*4 + 2)*32 + lane] = A2;
        pp[(w*4 + 3)*32 + lane] = A3;
    }
    __syncthreads();

    if (tid < 128) {
        const int f = tid;
        float av[4];
        #pragma unroll
        for (int t = 0; t < 4; t++) {
            float s = 0.f;
            #pragma unroll
            for (int w = 0; w < 16; w++) s += part[(w*4 + t)*FE + f];
            av[t] = s;
        }
        int   gg[4] = {sg[0], sg[1], sg[2], sg[3]};
        float pp[4] = {sp[0], sp[1], sp[2], sp[3]};
        float bi = bias[e*FE + f];
        #pragma unroll
        for (int t = 0; t < 4; t++) {
            float sum = bi;
            #pragma unroll
            for (int t2 = 0; t2 < 4; t2++)
                if (gg[t2] == gg[t]) sum += pp[t2] * av[t2];
            Wsm[t*FE + f] = pp[t] * fmaxf(sum, 0.f);
        }
    }
    __syncthreads();

    // --- down-projection: thread owns 2 d' columns, stream f2 rows ---
    {
        const float* f2p = f2 + (size_t)e*FE*DM + tid*2;
        float o0x=0,o0y=0,o1x=0,o1y=0,o2x=0,o2y=0,o3x=0,o3y=0;
        #pragma unroll 4
        for (int f = 0; f < FE; f++) {
            float2 v = *reinterpret_cast<const float2*>(f2p + (size_t)f*DM);
            float w0 = Wsm[0*FE+f], w1 = Wsm[1*FE+f];
            float w2 = Wsm[2*FE+f], w3 = Wsm[3*FE+f];
            o0x += w0*v.x; o0y += w0*v.y;
            o1x += w1*v.x; o1y += w1*v.y;
            o2x += w2*v.x; o2y += w2*v.y;
            o3x += w3*v.x; o3y += w3*v.y;
        }
        float* ob = out + (size_t)b*SEQ*DM + tid*2;
        float* r0 = ob + (size_t)(sg[0]*4 + 0)*DM;
        float* r1 = ob + (size_t)(sg[1]*4 + 1)*DM;
        float* r2 = ob + (size_t)(sg[2]*4 + 2)*DM;
        float* r3 = ob + (size_t)(sg[3]*4 + 3)*DM;
        atomicAdd(r0,   o0x); atomicAdd(r0+1, o0y);
        atomicAdd(r1,   o1x); atomicAdd(r1+1, o1y);
        atomicAdd(r2,   o2x); atomicAdd(r2+1, o2y);
        atomicAdd(r3,   o3x); atomicAdd(r3+1, o3y);
    }
}

extern "C" void kernel_launch(void* const* d_in, const int* in_sizes, int n_in,
                              void* d_out, int out_size)
{
    const float* x    = (const float*)d_in[0];
    const float* ctrl = (const float*)d_in[1];
    const float* f1   = (const float*)d_in[2];
    const float* bias = (const float*)d_in[3];
    const float* f2   = (const float*)d_in[4];
    float* out = (float*)d_out;

    cudaFuncSetAttribute(k_logits, cudaFuncAttributeMaxDynamicSharedMemorySize, SMEM1);
    cudaFuncSetAttribute(k_expert, cudaFuncAttributeMaxDynamicSharedMemorySize, SMEM2);

    k_logits<<<256, 256, SMEM1>>>(x, ctrl, out);
    k_expert<<<BATCH*NEXP, 512, SMEM2>>>(x, f1, bias, f2, out);
}

// round 6
// speedup vs baseline: 2.2421x; 1.0532x over previous
#include <cuda_runtime.h>
#include <cstdint>
#include <math.h>

#define DM   1024
#define NEXP 32
#define FE   128
#define TT   4
#define BATCH 4
#define SEQ  4096
#define NTOK (BATCH*SEQ)   // 16384
#define NGRP (SEQ/TT)      // 1024

typedef unsigned long long ull;

// scratch (device global; no allocation)
__device__ float g_logitsT[BATCH*TT*NEXP*NGRP];          // 2MB  [(b*4+t)*32+e][g]

__device__ __forceinline__ ull pack2(float a, float b) {
    ull r; asm("mov.b64 %0,{%1,%2};" : "=l"(r) : "f"(a), "f"(b)); return r;
}
__device__ __forceinline__ void unpack2(ull v, float& a, float& b) {
    asm("mov.b64 {%0,%1},%2;" : "=f"(a), "=f"(b) : "l"(v));
}
__device__ __forceinline__ void ffma2(ull& d, ull a, ull b) {
    asm("fma.rn.f32x2 %0,%1,%2,%0;" : "+l"(d) : "l"(a), "l"(b));
}
__device__ __forceinline__ void cp_async16(unsigned int dst, const void* src) {
    asm volatile("cp.async.cg.shared.global [%0], [%1], 16;\n" :: "r"(dst), "l"(src));
}
#define CP_COMMIT() asm volatile("cp.async.commit_group;\n" ::)
#define CP_WAIT0()  asm volatile("cp.async.wait_group 0;\n" ::)

// ---------------------------------------------------------------------------
// K1: zero output + logits GEMM. 128 blocks x 512 threads.
// warp = (eq, ks): eq = expert quarter (8 experts), ks = k-slice (8 k per
// 32-k chunk). Thread tile: 4 tokens x 8 experts (16 f32x2 accs = 32 regs).
// Full controller in smem (128KB); x staged once, cp.async double-buffered.
// ---------------------------------------------------------------------------
#define XROW 36                          // floats per staged token row
#define XBUF_BYTES (128*XROW*4)          // 18432
#define SMEM1 (131072 + 2*XBUF_BYTES)    // 167936

__global__ void __launch_bounds__(512, 1)
k_logits(const float* __restrict__ x, const float* __restrict__ ctrl,
         float* __restrict__ out)
{
    extern __shared__ char smraw[];
    ull*   ctrl_s = reinterpret_cast<ull*>(smraw);              // [1024k][16 ull]
    float* xbuf0  = reinterpret_cast<float*>(smraw + 131072);
    float* xbuf1  = reinterpret_cast<float*>(smraw + 131072 + XBUF_BYTES);

    const int tid = threadIdx.x;
    const int tg  = tid & 31;        // token group (lane)
    const int w   = tid >> 5;        // warp
    const int eq  = w >> 2;          // expert quarter (0..3)
    const int ks  = w & 3;           // k slice (0..3)
    const int tb  = blockIdx.x;      // token tile (128 tokens)
    const float* xblk = x + (size_t)tb * 128 * DM;

    // fire-and-forget zero of this block's output slab
    {
        float4 z = make_float4(0.f, 0.f, 0.f, 0.f);
        float4* op = reinterpret_cast<float4*>(out) + (size_t)tb * 32768;
        #pragma unroll
        for (int i = 0; i < 64; i++) op[tid + i*512] = z;
    }

    const unsigned int xs0 = (unsigned int)__cvta_generic_to_shared(xbuf0);
    const unsigned int xs1 = (unsigned int)__cvta_generic_to_shared(xbuf1);

    // stage chunk 0: 128 tok x 32 k, 2 quads per thread
    {
        #pragma unroll
        for (int i = 0; i < 2; i++) {
            int q = tid + i*512;             // 0..1023
            int tok = q >> 3, kq = q & 7;
            cp_async16(xs0 + tok*144 + kq*16, xblk + (size_t)tok*DM + kq*4);
        }
        CP_COMMIT();
    }

    // load full controller into smem: [k][32 floats] natural layout
    {
        const float4* cg4 = reinterpret_cast<const float4*>(ctrl);
        float4* cs4 = reinterpret_cast<float4*>(ctrl_s);
        #pragma unroll
        for (int i = 0; i < 16; i++) cs4[tid + i*512] = cg4[tid + i*512];
    }

    ull acc[4][4];
    #pragma unroll
    for (int i = 0; i < 4; i++)
        #pragma unroll
        for (int p = 0; p < 4; p++) acc[i][p] = 0ull;

    for (int c = 0; c < 32; c++) {
        CP_WAIT0();
        __syncthreads();
        if (c < 31) {
            unsigned int dst = ((c+1) & 1) ? xs1 : xs0;
            #pragma unroll
            for (int i = 0; i < 2; i++) {
                int q = tid + i*512;
                int tok = q >> 3, kq = q & 7;
                cp_async16(dst + tok*144 + kq*16,
                           xblk + (size_t)tok*DM + (c+1)*32 + kq*4);
            }
            CP_COMMIT();
        }
        const float* xb = (c & 1) ? xbuf1 : xbuf0;

        // thread's 8-k window: k = c*32 + ks*8 + u
        float xr[4][8];
        #pragma unroll
        for (int i = 0; i < 4; i++) {
            const float4* p4 = reinterpret_cast<const float4*>(
                xb + (tg + 32*i)*XROW + ks*8);
            float4 v0 = p4[0], v1 = p4[1];
            xr[i][0]=v0.x; xr[i][1]=v0.y; xr[i][2]=v0.z; xr[i][3]=v0.w;
            xr[i][4]=v1.x; xr[i][5]=v1.y; xr[i][6]=v1.z; xr[i][7]=v1.w;
        }

        #pragma unroll
        for (int u = 0; u < 8; u++) {
            const ulonglong2* cb = reinterpret_cast<const ulonglong2*>(
                ctrl_s + (size_t)(c*32 + ks*8 + u)*16 + eq*4);
            ulonglong2 q0 = cb[0], q1 = cb[1];
            ull cu0 = q0.x, cu1 = q0.y, cu2 = q1.x, cu3 = q1.y;
            #pragma unroll
            for (int i = 0; i < 4; i++) {
                ull x2 = pack2(xr[i][u], xr[i][u]);
                ffma2(acc[i][0], x2, cu0);
                ffma2(acc[i][1], x2, cu1);
                ffma2(acc[i][2], x2, cu2);
                ffma2(acc[i][3], x2, cu3);
            }
        }
    }
    __syncthreads();

    // reduce over 4 k-slices via smem (reuse ctrl_s): red[eq][ks][tok][4]
    ull* red = ctrl_s;
    #pragma unroll
    for (int i = 0; i < 4; i++)
        #pragma unroll
        for (int p = 0; p < 4; p++)
            red[(((size_t)(eq*4 + ks)*128) + (tg + 32*i))*4 + p] = acc[i][p];
    __syncthreads();

    #pragma unroll
    for (int j = 0; j < 4; j++) {
        int s = tid*4 + j;               // 0..2047: item = (tok, pair)
        int tok = s >> 4, pr = s & 15;   // pr: expert pair 0..15
        int peq = pr >> 2, pp = pr & 3;
        float lo = 0.f, hi = 0.f;
        #pragma unroll
        for (int k2 = 0; k2 < 4; k2++) {
            float a, b;
            unpack2(red[(((size_t)(peq*4 + k2)*128) + tok)*4 + pp], a, b);
            lo += a; hi += b;
        }
        int gt = tb*128 + tok;
        int b  = gt >> 12;
        int sg = gt & 4095;
        int g  = sg >> 2, t = sg & 3;
        float tbk = (float)t * (1e-6f / 3.0f);   // linspace(0,1e-6,4)[t]
        int row = (b*4 + t)*32 + 2*pr;
        g_logitsT[(size_t)row*1024 + g]     = lo + tbk;
        g_logitsT[(size_t)(row+1)*1024 + g] = hi + tbk;
    }
}

// ---------------------------------------------------------------------------
// K2: selection + up-proj + down-proj + scatter-add, split over 4 f-slices.
// grid 512 = (b, e, fs) x 256 threads. Up-proj is independent per f, so each
// slice computes its own W[t][32] and adds its partial down-projection.
// ---------------------------------------------------------------------------
__global__ void __launch_bounds__(256, 4)
k_expert(const float* __restrict__ x, const float* __restrict__ f1,
         const float* __restrict__ bias, const float* __restrict__ f2,
         float* __restrict__ out)
{
    __shared__ float xs[4][DM];          // 16KB
    __shared__ float part[8][4][32];     // 4KB
    __shared__ float avs[4][32];
    __shared__ float Wsm[4][32];
    __shared__ int   sg[4];
    __shared__ float sp[4];
    __shared__ float rm[4][2];
    __shared__ int   rmi[4][2];
    __shared__ float rs[4][2];
    __shared__ float rmf[4];

    const int tid  = threadIdx.x;
    const int lane = tid & 31;
    const int b  = blockIdx.x >> 7;
    const int e  = (blockIdx.x >> 2) & 31;
    const int fs = blockIdx.x & 3;

    // --- selection: 64-thread group per t ---
    {
        const int ts = tid >> 6;
        const int gt = tid & 63;
        const int wp = (tid >> 5) & 1;
        const float* L = g_logitsT + ((size_t)((b*4 + ts)*32 + e) << 10);

        float m = -3.4e38f; int mi = 0;
        #pragma unroll
        for (int j = 0; j < 16; j++) {
            int i = gt + j*64;
            float v = L[i];
            if (v > m) { m = v; mi = i; }
        }
        #pragma unroll
        for (int o = 16; o; o >>= 1) {
            float om = __shfl_down_sync(0xffffffffu, m, o);
            int   oi = __shfl_down_sync(0xffffffffu, mi, o);
            if (om > m || (om == m && oi < mi)) { m = om; mi = oi; }
        }
        if (lane == 0) { rm[ts][wp] = m; rmi[ts][wp] = mi; }
        __syncthreads();
        if (tid < 4) {
            float mm = rm[tid][0]; int mmi = rmi[tid][0];
            if (rm[tid][1] > mm || (rm[tid][1] == mm && rmi[tid][1] < mmi)) {
                mm = rm[tid][1]; mmi = rmi[tid][1];
            }
            rmf[tid] = mm; sg[tid] = mmi;
        }
        __syncthreads();
        m = rmf[ts];

        float s = 0.f;
        #pragma unroll
        for (int j = 0; j < 16; j++) s += expf(L[gt + j*64] - m);
        #pragma unroll
        for (int o = 16; o; o >>= 1) s += __shfl_down_sync(0xffffffffu, s, o);
        if (lane == 0) rs[ts][wp] = s;
        __syncthreads();
        if (tid < 4) sp[tid] = 1.0f / (rs[tid][0] + rs[tid][1]);
        __syncthreads();
    }

    // --- load the 4 selected token rows into smem ---
    {
        const int ts = tid >> 6;
        const int gt = tid & 63;
        const float* xr = x + ((size_t)b*SEQ + sg[ts]*4 + ts) * DM;
        float4* dst = reinterpret_cast<float4*>(xs[ts]);
        const float4* src = reinterpret_cast<const float4*>(xr);
        #pragma unroll
        for (int i = 0; i < 4; i++) dst[gt + i*64] = src[gt + i*64];
    }
    __syncthreads();

    // --- up-projection for this block's 32 f's: warp w owns 128 d ---
    {
        const int w = tid >> 5;
        float a0 = 0.f, a1 = 0.f, a2 = 0.f, a3 = 0.f;
        const float* f1p = f1 + (size_t)(w*128)*(NEXP*FE) + e*FE + fs*32 + lane;
        const float* x0 = xs[0] + w*128;
        const float* x1 = xs[1] + w*128;
        const float* x2 = xs[2] + w*128;
        const float* x3 = xs[3] + w*128;
        #pragma unroll 8
        for (int d = 0; d < 128; d++) {
            float wv = f1p[(size_t)d * (NEXP*FE)];
            a0 += x0[d]*wv; a1 += x1[d]*wv; a2 += x2[d]*wv; a3 += x3[d]*wv;
        }
        part[w][0][lane] = a0; part[w][1][lane] = a1;
        part[w][2][lane] = a2; part[w][3][lane] = a3;
    }
    __syncthreads();

    if (tid < 128) {
        const int t = tid >> 5, f = tid & 31;
        float s = 0.f;
        #pragma unroll
        for (int w = 0; w < 8; w++) s += part[w][t][f];
        avs[t][f] = s;
    }
    __syncthreads();

    if (tid < 32) {
        const int f = tid;
        float av[4] = {avs[0][f], avs[1][f], avs[2][f], avs[3][f]};
        int   gg[4] = {sg[0], sg[1], sg[2], sg[3]};
        float pp[4] = {sp[0], sp[1], sp[2], sp[3]};
        float bi = bias[e*FE + fs*32 + f];
        #pragma unroll
        for (int t = 0; t < 4; t++) {
            float sum = bi;
            #pragma unroll
            for (int t2 = 0; t2 < 4; t2++)
                if (gg[t2] == gg[t]) sum += pp[t2] * av[t2];
            Wsm[t][f] = pp[t] * fmaxf(sum, 0.f);
        }
    }
    __syncthreads();

    // --- down-projection: thread owns 4 d' columns, 32 f rows ---
    {
        float o0[4] = {0,0,0,0}, o1[4] = {0,0,0,0};
        float o2[4] = {0,0,0,0}, o3[4] = {0,0,0,0};
        const float* f2p = f2 + (size_t)e*FE*DM + (size_t)(fs*32)*DM + tid*4;
        #pragma unroll 4
        for (int f = 0; f < 32; f++) {
            float4 v = *reinterpret_cast<const float4*>(f2p + (size_t)f*DM);
            float w0 = Wsm[0][f], w1 = Wsm[1][f], w2 = Wsm[2][f], w3 = Wsm[3][f];
            o0[0] += w0*v.x; o0[1] += w0*v.y; o0[2] += w0*v.z; o0[3] += w0*v.w;
            o1[0] += w1*v.x; o1[1] += w1*v.y; o1[2] += w1*v.z; o1[3] += w1*v.w;
            o2[0] += w2*v.x; o2[1] += w2*v.y; o2[2] += w2*v.z; o2[3] += w2*v.w;
            o3[0] += w3*v.x; o3[1] += w3*v.y; o3[2] += w3*v.z; o3[3] += w3*v.w;
        }
        float* ob = out + (size_t)b*SEQ*DM + tid*4;
        float* r0 = ob + (size_t)(sg[0]*4 + 0)*DM;
        float* r1 = ob + (size_t)(sg[1]*4 + 1)*DM;
        float* r2 = ob + (size_t)(sg[2]*4 + 2)*DM;
        float* r3 = ob + (size_t)(sg[3]*4 + 3)*DM;
        #pragma unroll
        for (int j = 0; j < 4; j++) atomicAdd(r0 + j, o0[j]);
        #pragma unroll
        for (int j = 0; j < 4; j++) atomicAdd(r1 + j, o1[j]);
        #pragma unroll
        for (int j = 0; j < 4; j++) atomicAdd(r2 + j, o2[j]);
        #pragma unroll
        for (int j = 0; j < 4; j++) atomicAdd(r3 + j, o3[j]);
    }
}

extern "C" void kernel_launch(void* const* d_in, const int* in_sizes, int n_in,
                              void* d_out, int out_size)
{
    const float* x    = (const float*)d_in[0];
    const float* ctrl = (const float*)d_in[1];
    const float* f1   = (const float*)d_in[2];
    const float* bias = (const float*)d_in[3];
    const float* f2   = (const float*)d_in[4];
    float* out = (float*)d_out;

    cudaFuncSetAttribute(k_logits, cudaFuncAttributeMaxDynamicSharedMemorySize, SMEM1);

    k_logits<<<128, 512, SMEM1>>>(x, ctrl, out);
    k_expert<<<BATCH*NEXP*4, 256>>>(x, f1, bias, f2, out);
}

// round 7
// speedup vs baseline: 2.3259x; 1.0374x over previous
#include <cuda_runtime.h>
#include <cstdint>
#include <math.h>

#define DM   1024
#define NEXP 32
#define FE   128
#define TT   4
#define BATCH 4
#define SEQ  4096
#define NTOK (BATCH*SEQ)   // 16384
#define NGRP (SEQ/TT)      // 1024

typedef unsigned long long ull;

// scratch (device globals; no allocation)
__device__ float g_logitsT[BATCH*TT*NEXP*NGRP];   // 2MB [(b*4+t)*32+e][g]
__device__ int   g_selg[BATCH*TT*NEXP];
__device__ float g_selp[BATCH*TT*NEXP];

__device__ __forceinline__ ull pack2(float a, float b) {
    ull r; asm("mov.b64 %0,{%1,%2};" : "=l"(r) : "f"(a), "f"(b)); return r;
}
__device__ __forceinline__ void unpack2(ull v, float& a, float& b) {
    asm("mov.b64 {%0,%1},%2;" : "=f"(a), "=f"(b) : "l"(v));
}
__device__ __forceinline__ void ffma2(ull& d, ull a, ull b) {
    asm("fma.rn.f32x2 %0,%1,%2,%0;" : "+l"(d) : "l"(a), "l"(b));
}

// ---------------------------------------------------------------------------
// K1: zero output + logits GEMM. 128 blocks x 512 threads.
// warp = (eq, ks): eq = expert quarter (8 experts), ks = k-slice of chunk.
// Thread: 4 tokens x 8 experts. x staged transposed [k][tok] pad-129:
// STS conflict-free (bank = 4*kq + tok covers all 32), compute reads are
// scalar LDS lane-stride-1 (conflict-free). Full controller in smem.
// ---------------------------------------------------------------------------
#define XKROW 129
#define XKBUF (32*XKROW)                        // floats per buffer (4128)
#define SMEM1 (131072 + 2*XKBUF*4)              // 164096

__global__ void __launch_bounds__(512, 1)
k_logits(const float* __restrict__ x, const float* __restrict__ ctrl,
         float* __restrict__ out)
{
    extern __shared__ char smraw[];
    ull*   ctrl_s = reinterpret_cast<ull*>(smraw);              // [1024k][16 ull]
    float* xk0    = reinterpret_cast<float*>(smraw + 131072);   // [32][129]
    float* xk1    = xk0 + XKBUF;

    const int tid = threadIdx.x;
    const int tg  = tid & 31;        // lane
    const int w   = tid >> 5;
    const int eq  = w >> 2;          // expert quarter
    const int ks  = w & 3;           // k slice (8 k of 32-k chunk)
    const int tb  = blockIdx.x;
    const float* xblk = x + (size_t)tb * 128 * DM;

    // fire-and-forget zero of this block's output slab
    {
        float4 z = make_float4(0.f, 0.f, 0.f, 0.f);
        float4* op = reinterpret_cast<float4*>(out) + (size_t)tb * 32768;
        #pragma unroll
        for (int i = 0; i < 64; i++) op[tid + i*512] = z;
    }

    // staging geometry: q = tid + i*512 (i<2); tok = q>>3, kq = q&7
    const int s_tok0 = tid >> 3;
    const int s_kq   = tid & 7;

    // prologue: stage chunk 0
    float4 r0, r1;
    r0 = *reinterpret_cast<const float4*>(xblk + (size_t)s_tok0*DM + s_kq*4);
    r1 = *reinterpret_cast<const float4*>(xblk + (size_t)(s_tok0+64)*DM + s_kq*4);

    // load full controller into smem: [k][32 floats] natural layout
    {
        const float4* cg4 = reinterpret_cast<const float4*>(ctrl);
        float4* cs4 = reinterpret_cast<float4*>(ctrl_s);
        #pragma unroll
        for (int i = 0; i < 16; i++) cs4[tid + i*512] = cg4[tid + i*512];
    }
    {
        const float* rr0 = reinterpret_cast<const float*>(&r0);
        const float* rr1 = reinterpret_cast<const float*>(&r1);
        #pragma unroll
        for (int j = 0; j < 4; j++) {
            xk0[(s_kq*4 + j)*XKROW + s_tok0]      = rr0[j];
            xk0[(s_kq*4 + j)*XKROW + s_tok0 + 64] = rr1[j];
        }
    }
    __syncthreads();

    ull acc[4][4];
    #pragma unroll
    for (int i = 0; i < 4; i++)
        #pragma unroll
        for (int p = 0; p < 4; p++) acc[i][p] = 0ull;

    for (int c = 0; c < 32; c++) {
        // issue next chunk's loads first
        if (c < 31) {
            r0 = *reinterpret_cast<const float4*>(
                xblk + (size_t)s_tok0*DM + (c+1)*32 + s_kq*4);
            r1 = *reinterpret_cast<const float4*>(
                xblk + (size_t)(s_tok0+64)*DM + (c+1)*32 + s_kq*4);
        }

        const float* xb = (c & 1) ? xk1 : xk0;
        #pragma unroll
        for (int u = 0; u < 8; u++) {
            const ulonglong2* cb = reinterpret_cast<const ulonglong2*>(
                ctrl_s + (size_t)(c*32 + ks*8 + u)*16 + eq*4);
            ulonglong2 q0 = cb[0], q1 = cb[1];
            ull cu0 = q0.x, cu1 = q0.y, cu2 = q1.x, cu3 = q1.y;
            const float* xrow = xb + (ks*8 + u)*XKROW + tg;
            #pragma unroll
            for (int i = 0; i < 4; i++) {
                float xf = xrow[32*i];
                ull x2 = pack2(xf, xf);
                ffma2(acc[i][0], x2, cu0);
                ffma2(acc[i][1], x2, cu1);
                ffma2(acc[i][2], x2, cu2);
                ffma2(acc[i][3], x2, cu3);
            }
        }

        if (c < 31) {
            float* bw = (c & 1) ? xk0 : xk1;
            const float* rr0 = reinterpret_cast<const float*>(&r0);
            const float* rr1 = reinterpret_cast<const float*>(&r1);
            #pragma unroll
            for (int j = 0; j < 4; j++) {
                bw[(s_kq*4 + j)*XKROW + s_tok0]      = rr0[j];
                bw[(s_kq*4 + j)*XKROW + s_tok0 + 64] = rr1[j];
            }
        }
        __syncthreads();
    }

    // reduce over 4 k-slices via smem (reuse ctrl_s)
    ull* red = ctrl_s;
    #pragma unroll
    for (int i = 0; i < 4; i++)
        #pragma unroll
        for (int p = 0; p < 4; p++)
            red[(((size_t)(eq*4 + ks)*128) + (tg + 32*i))*4 + p] = acc[i][p];
    __syncthreads();

    #pragma unroll
    for (int j = 0; j < 4; j++) {
        int s = tid*4 + j;               // item = (tok, expert-pair)
        int tok = s >> 4, pr = s & 15;
        int peq = pr >> 2, pp = pr & 3;
        float lo = 0.f, hi = 0.f;
        #pragma unroll
        for (int k2 = 0; k2 < 4; k2++) {
            float a, b;
            unpack2(red[(((size_t)(peq*4 + k2)*128) + tok)*4 + pp], a, b);
            lo += a; hi += b;
        }
        int gt = tb*128 + tok;
        int b  = gt >> 12;
        int sg = gt & 4095;
        int g  = sg >> 2, t = sg & 3;
        float tbk = (float)t * (1e-6f / 3.0f);   // linspace(0,1e-6,4)[t]
        int row = (b*4 + t)*32 + 2*pr;
        g_logitsT[(size_t)row*1024 + g]     = lo + tbk;
        g_logitsT[(size_t)(row+1)*1024 + g] = hi + tbk;
    }
}

// ---------------------------------------------------------------------------
// K_sel: one block per (b,t,e) row: argmax + softmax denominator over 1024 g.
// ---------------------------------------------------------------------------
__global__ void __launch_bounds__(256, 8)
k_sel()
{
    __shared__ float rm[8];
    __shared__ int   rmi[8];
    __shared__ float rs[8];
    __shared__ float mfin;

    const int tid  = threadIdx.x;
    const int lane = tid & 31;
    const int wp   = tid >> 5;
    const float* L = g_logitsT + ((size_t)blockIdx.x << 10);

    float m = -3.4e38f; int mi = 0;
    #pragma unroll
    for (int j = 0; j < 4; j++) {
        int i = tid + j*256;
        float v = L[i];
        if (v > m) { m = v; mi = i; }
    }
    #pragma unroll
    for (int o = 16; o; o >>= 1) {
        float om = __shfl_down_sync(0xffffffffu, m, o);
        int   oi = __shfl_down_sync(0xffffffffu, mi, o);
        if (om > m || (om == m && oi < mi)) { m = om; mi = oi; }
    }
    if (lane == 0) { rm[wp] = m; rmi[wp] = mi; }
    __syncthreads();
    if (tid == 0) {
        #pragma unroll
        for (int w = 1; w < 8; w++) {
            if (rm[w] > m || (rm[w] == m && rmi[w] < mi)) { m = rm[w]; mi = rmi[w]; }
        }
        g_selg[blockIdx.x] = mi;
        mfin = m;
    }
    __syncthreads();
    m = mfin;

    float s = 0.f;
    #pragma unroll
    for (int j = 0; j < 4; j++) s += expf(L[tid + j*256] - m);
    #pragma unroll
    for (int o = 16; o; o >>= 1) s += __shfl_down_sync(0xffffffffu, s, o);
    if (lane == 0) rs[wp] = s;
    __syncthreads();
    if (tid == 0) {
        float tot = 0.f;
        #pragma unroll
        for (int w = 0; w < 8; w++) tot += rs[w];
        g_selp[blockIdx.x] = 1.0f / tot;
    }
}

// ---------------------------------------------------------------------------
// K2: up-proj + down-proj + scatter-add, split over 4 f-slices.
// grid 512 = (b, e, fs) x 256 threads.
// ---------------------------------------------------------------------------
__global__ void __launch_bounds__(256, 4)
k_expert(const float* __restrict__ x, const float* __restrict__ f1,
         const float* __restrict__ bias, const float* __restrict__ f2,
         float* __restrict__ out)
{
    __shared__ float xs[4][DM];          // 16KB
    __shared__ float part[8][4][32];     // 4KB
    __shared__ float avs[4][32];
    __shared__ float Wsm[4][32];
    __shared__ int   sg[4];
    __shared__ float sp[4];

    const int tid  = threadIdx.x;
    const int lane = tid & 31;
    const int b  = blockIdx.x >> 7;
    const int e  = (blockIdx.x >> 2) & 31;
    const int fs = blockIdx.x & 3;

    if (tid < 4) {
        sg[tid] = g_selg[(b*4 + tid)*32 + e];
        sp[tid] = g_selp[(b*4 + tid)*32 + e];
    }
    __syncthreads();

    // --- load the 4 selected token rows into smem ---
    {
        const int ts = tid >> 6;
        const int gt = tid & 63;
        const float* xr = x + ((size_t)b*SEQ + sg[ts]*4 + ts) * DM;
        float4* dst = reinterpret_cast<float4*>(xs[ts]);
        const float4* src = reinterpret_cast<const float4*>(xr);
        #pragma unroll
        for (int i = 0; i < 4; i++) dst[gt + i*64] = src[gt + i*64];
    }
    __syncthreads();

    // --- up-projection for this block's 32 f's: warp w owns 128 d ---
    {
        const int w = tid >> 5;
        float a0 = 0.f, a1 = 0.f, a2 = 0.f, a3 = 0.f;
        const float* f1p = f1 + (size_t)(w*128)*(NEXP*FE) + e*FE + fs*32 + lane;
        const float* x0 = xs[0] + w*128;
        const float* x1 = xs[1] + w*128;
        const float* x2 = xs[2] + w*128;
        const float* x3 = xs[3] + w*128;
        #pragma unroll 16
        for (int d = 0; d < 128; d++) {
            float wv = f1p[(size_t)d * (NEXP*FE)];
            a0 += x0[d]*wv; a1 += x1[d]*wv; a2 += x2[d]*wv; a3 += x3[d]*wv;
        }
        part[w][0][lane] = a0; part[w][1][lane] = a1;
        part[w][2][lane] = a2; part[w][3][lane] = a3;
    }
    __syncthreads();

    if (tid < 128) {
        const int t = tid >> 5, f = tid & 31;
        float s = 0.f;
        #pragma unroll
        for (int w = 0; w < 8; w++) s += part[w][t][f];
        avs[t][f] = s;
    }
    __syncthreads();

    if (tid < 32) {
        const int f = tid;
        float av[4] = {avs[0][f], avs[1][f], avs[2][f], avs[3][f]};
        int   gg[4] = {sg[0], sg[1], sg[2], sg[3]};
        float pp[4] = {sp[0], sp[1], sp[2], sp[3]};
        float bi = bias[e*FE + fs*32 + f];
        #pragma unroll
        for (int t = 0; t < 4; t++) {
            float sum = bi;
            #pragma unroll
            for (int t2 = 0; t2 < 4; t2++)
                if (gg[t2] == gg[t]) sum += pp[t2] * av[t2];
            Wsm[t][f] = pp[t] * fmaxf(sum, 0.f);
        }
    }
    __syncthreads();

    // --- down-projection: thread owns 4 d' columns, 32 f rows ---
    {
        float o0[4] = {0,0,0,0}, o1[4] = {0,0,0,0};
        float o2[4] = {0,0,0,0}, o3[4] = {0,0,0,0};
        const float* f2p = f2 + (size_t)e*FE*DM + (size_t)(fs*32)*DM + tid*4;
        #pragma unroll 8
        for (int f = 0; f < 32; f++) {
            float4 v = *reinterpret_cast<const float4*>(f2p + (size_t)f*DM);
            float w0 = Wsm[0][f], w1 = Wsm[1][f], w2 = Wsm[2][f], w3 = Wsm[3][f];
            o0[0] += w0*v.x; o0[1] += w0*v.y; o0[2] += w0*v.z; o0[3] += w0*v.w;
            o1[0] += w1*v.x; o1[1] += w1*v.y; o1[2] += w1*v.z; o1[3] += w1*v.w;
            o2[0] += w2*v.x; o2[1] += w2*v.y; o2[2] += w2*v.z; o2[3] += w2*v.w;
            o3[0] += w3*v.x; o3[1] += w3*v.y; o3[2] += w3*v.z; o3[3] += w3*v.w;
        }
        float* ob = out + (size_t)b*SEQ*DM + tid*4;
        float* r0 = ob + (size_t)(sg[0]*4 + 0)*DM;
        float* r1 = ob + (size_t)(sg[1]*4 + 1)*DM;
        float* r2 = ob + (size_t)(sg[2]*4 + 2)*DM;
        float* r3 = ob + (size_t)(sg[3]*4 + 3)*DM;
        #pragma unroll
        for (int j = 0; j < 4; j++) atomicAdd(r0 + j, o0[j]);
        #pragma unroll
        for (int j = 0; j < 4; j++) atomicAdd(r1 + j, o1[j]);
        #pragma unroll
        for (int j = 0; j < 4; j++) atomicAdd(r2 + j, o2[j]);
        #pragma unroll
        for (int j = 0; j < 4; j++) atomicAdd(r3 + j, o3[j]);
    }
}

extern "C" void kernel_launch(void* const* d_in, const int* in_sizes, int n_in,
                              void* d_out, int out_size)
{
    const float* x    = (const float*)d_in[0];
    const float* ctrl = (const float*)d_in[1];
    const float* f1   = (const float*)d_in[2];
    const float* bias = (const float*)d_in[3];
    const float* f2   = (const float*)d_in[4];
    float* out = (float*)d_out;

    cudaFuncSetAttribute(k_logits, cudaFuncAttributeMaxDynamicSharedMemorySize, SMEM1);

    k_logits<<<128, 512, SMEM1>>>(x, ctrl, out);
    k_sel<<<BATCH*TT*NEXP, 256>>>();
    k_expert<<<BATCH*NEXP*4, 256>>>(x, f1, bias, f2, out);
}